// round 17
// baseline (speedup 1.0000x reference)
#include <cuda_runtime.h>
#include <cuda_bf16.h>
#include <math.h>
#include <stdint.h>

// ---------------- problem constants ----------------
#define BQ    2
#define TT    8
#define CDIM  192
#define NSP   576
#define TOK   9216
#define DI    384
#define DS    16
#define DTR   12
#define MLPH  768
#define XZW   1536

typedef __nv_bfloat16 bf16;

// ---------------- scratch ----------------
__device__ bf16  g_xn_bf[TOK*CDIM];
__device__ float g_short[TOK*CDIM];
__device__ bf16  g_xz_bf[TOK*XZW];
__device__ bf16  g_u_bf[2][TOK*DI];
__device__ float g_delta[2][TOK*DI];
__device__ float g_dbc[2][TOK*64];
__device__ bf16  g_y_bf[TOK*2*DI];
__device__ float g_x2[TOK*CDIM];
__device__ bf16  g_h_bf[TOK*CDIM];
__device__ bf16  g_hid_bf[TOK*MLPH];
__device__ bf16  g_Win_bf[XZW*CDIM];
__device__ bf16  g_W12_bf[CDIM*2*DI];
__device__ bf16  g_xpwP_bf[2][64*DI];
__device__ bf16  g_w1_bf[MLPH*CDIM];
__device__ bf16  g_w2_bf[CDIM*MLPH];
__device__ float g_A[2][DI*DS];
__device__ float g_cwT[2][4*DI];
__device__ float g_dpwT[2][DTR*DI];

// ---------------- helpers ----------------
__device__ __forceinline__ uint32_t packbf(float lo, float hi) {
    uint32_t r;
    asm("cvt.rn.bf16x2.f32 %0, %1, %2;" : "=r"(r) : "f"(hi), "f"(lo));
    return r;
}
__device__ __forceinline__ void mma_bf16(float c[4], const uint32_t a[4], const uint32_t b[2]) {
    asm("mma.sync.aligned.m16n8k16.row.col.f32.bf16.bf16.f32 "
        "{%0,%1,%2,%3}, {%4,%5,%6,%7}, {%8,%9}, {%0,%1,%2,%3};"
        : "+f"(c[0]), "+f"(c[1]), "+f"(c[2]), "+f"(c[3])
        : "r"(a[0]), "r"(a[1]), "r"(a[2]), "r"(a[3]), "r"(b[0]), "r"(b[1]));
}
__device__ __forceinline__ void ldsm_x4(uint32_t& r0, uint32_t& r1, uint32_t& r2, uint32_t& r3,
                                        uint32_t addr) {
    asm volatile("ldmatrix.sync.aligned.m8n8.x4.shared.b16 {%0,%1,%2,%3}, [%4];"
                 : "=r"(r0), "=r"(r1), "=r"(r2), "=r"(r3) : "r"(addr));
}
__device__ __forceinline__ uint32_t smem_u32(const void* p) {
    return (uint32_t)__cvta_generic_to_shared(p);
}
__device__ __forceinline__ void cpa16(uint32_t dst, const void* src) {
    asm volatile("cp.async.ca.shared.global [%0], [%1], 16;" :: "r"(dst), "l"(src));
}
#define CP_COMMIT() asm volatile("cp.async.commit_group;" ::: "memory")
#define CP_WAIT1()  asm volatile("cp.async.wait_group 1;" ::: "memory")
#define GRID_SYNC() cudaGridDependencySynchronize()

// ---------------- prep + fold (merged) ----------------
__global__ __launch_bounds__(384) void prepfold_kernel(
    const float* __restrict__ sAlog, const float* __restrict__ tAlog,
    const float* __restrict__ scw, const float* __restrict__ tcw,
    const float* __restrict__ sdpw, const float* __restrict__ tdpw,
    const float* __restrict__ sinw, const float* __restrict__ tinw,
    const float* __restrict__ sxpw, const float* __restrict__ txpw,
    const float* __restrict__ w1, const float* __restrict__ w2,
    const float* __restrict__ fw,
    const float* __restrict__ soutw, const float* __restrict__ toutw)
{
    GRID_SYNC();
    int tid = threadIdx.x;
    if (blockIdx.x < 768) {
        int i = blockIdx.x * 384 + tid;
        if (i < 2*DI*DS) {
            int m = i / (DI*DS), j = i % (DI*DS);
            g_A[m][j] = -expf(m ? tAlog[j] : sAlog[j]);
        }
        if (i < 2*4*DI) {
            int m = i / (4*DI), rem = i % (4*DI);
            int k = rem / DI, d = rem % DI;
            g_cwT[m][k*DI + d] = (m ? tcw : scw)[d*4 + k];
        }
        if (i < 2*DTR*DI) {
            int m = i / (DTR*DI), rem = i % (DTR*DI);
            int rr = rem / DI, d = rem % DI;
            g_dpwT[m][rr*DI + d] = (m ? tdpw : sdpw)[d*DTR + rr];
        }
        if (i < 2*64*DI) {
            int m = i / (64*DI), rem = i % (64*DI);
            int row = rem / DI;
            g_xpwP_bf[m][rem] = __float2bfloat16(
                (row < DTR + 2*DS) ? (m ? txpw : sxpw)[rem] : 0.f);
        }
        if (i < XZW*CDIM) {
            int row = i / CDIM;
            g_Win_bf[i] = __float2bfloat16((row < 768) ? sinw[i] : tinw[i - 768*CDIM]);
        }
        if (i < MLPH*CDIM) g_w1_bf[i] = __float2bfloat16(w1[i]);
        if (i < CDIM*MLPH) g_w2_bf[i] = __float2bfloat16(w2[i]);
    } else {
        __shared__ float fwS[8][192];
        int bx = blockIdx.x - 768;
        int m  = bx / 24;
        int c0 = (bx % 24) * 8;
        const float* ow = m ? toutw : soutw;
        for (int i = tid; i < 8*192; i += 384) {
            int c = i / 192, cp = i % 192;
            fwS[c][cp] = fw[(size_t)(c0 + c)*(2*CDIM) + m*CDIM + cp];
        }
        __syncthreads();
        float acc[8] = {0,0,0,0,0,0,0,0};
        #pragma unroll 4
        for (int cp = 0; cp < 192; cp++) {
            float owv = ow[(size_t)cp*DI + tid];
            #pragma unroll
            for (int c = 0; c < 8; c++) acc[c] = fmaf(fwS[c][cp], owv, acc[c]);
        }
        #pragma unroll
        for (int c = 0; c < 8; c++)
            g_W12_bf[(size_t)(c0 + c)*(2*DI) + m*DI + tid] = __float2bfloat16(acc[c]);
    }
}

// ---------------- LN1 ----------------
__global__ __launch_bounds__(256) void ln1_kernel(const float* __restrict__ src,
                                                  const float* __restrict__ w, const float* __restrict__ b)
{
    GRID_SYNC();
    __shared__ float s[CDIM][33];
    int bt = blockIdx.x;
    int n0 = blockIdx.y * 32;
    int tid = threadIdx.x;
    #pragma unroll
    for (int i = 0; i < 24; i++) {
        int idx = tid + 256*i;
        int c = idx >> 5, nl = idx & 31;
        s[c][nl] = src[((size_t)bt*CDIM + c)*NSP + n0 + nl];
    }
    __syncthreads();
    int warp = tid >> 5, lane = tid & 31;
    for (int jj = 0; jj < 4; jj++) {
        int tt = warp + 8*jj;
        float v[3][2];
        #pragma unroll
        for (int q = 0; q < 3; q++) {
            int c = 2*lane + 64*q;
            v[q][0] = s[c][tt];
            v[q][1] = s[c+1][tt];
        }
        float sum = 0.f;
        #pragma unroll
        for (int q = 0; q < 3; q++) sum += v[q][0] + v[q][1];
        #pragma unroll
        for (int o = 16; o > 0; o >>= 1) sum += __shfl_xor_sync(0xffffffffu, sum, o);
        float mean = sum * (1.f/CDIM);
        float qv = 0.f;
        #pragma unroll
        for (int q = 0; q < 3; q++) {
            float d0 = v[q][0]-mean, d1 = v[q][1]-mean;
            qv += d0*d0 + d1*d1;
        }
        #pragma unroll
        for (int o = 16; o > 0; o >>= 1) qv += __shfl_xor_sync(0xffffffffu, qv, o);
        float rstd = rsqrtf(qv * (1.f/CDIM) + 1e-5f);
        size_t tok = (size_t)bt*NSP + n0 + tt;
        #pragma unroll
        for (int q = 0; q < 3; q++) {
            int c = 2*lane + 64*q;
            float o0 = (v[q][0]-mean)*rstd*w[c]   + b[c];
            float o1 = (v[q][1]-mean)*rstd*w[c+1] + b[c+1];
            *reinterpret_cast<uint32_t*>(&g_xn_bf[tok*CDIM + c]) = packbf(o0, o1);
            *reinterpret_cast<float2*>(&g_short[tok*CDIM + c]) = make_float2(v[q][0], v[q][1]);
        }
    }
}

// ---------------- LN2 ----------------
__global__ void ln2_kernel(const float* __restrict__ src,
                           const float* __restrict__ w, const float* __restrict__ b)
{
    GRID_SYNC();
    int tok  = blockIdx.x * 4 + (threadIdx.x >> 5);
    int lane = threadIdx.x & 31;
    const float* base = src + (size_t)tok * CDIM;
    float v[3][2];
    #pragma unroll
    for (int q = 0; q < 3; q++) {
        float2 t = *reinterpret_cast<const float2*>(&base[2*lane + 64*q]);
        v[q][0] = t.x; v[q][1] = t.y;
    }
    float s = 0.f;
    #pragma unroll
    for (int q = 0; q < 3; q++) s += v[q][0] + v[q][1];
    #pragma unroll
    for (int o = 16; o > 0; o >>= 1) s += __shfl_xor_sync(0xffffffffu, s, o);
    float mean = s * (1.f / CDIM);
    float qv = 0.f;
    #pragma unroll
    for (int q = 0; q < 3; q++) {
        float d0 = v[q][0]-mean, d1 = v[q][1]-mean;
        qv += d0*d0 + d1*d1;
    }
    #pragma unroll
    for (int o = 16; o > 0; o >>= 1) qv += __shfl_xor_sync(0xffffffffu, qv, o);
    float rstd = rsqrtf(qv * (1.f / CDIM) + 1e-5f);
    #pragma unroll
    for (int q = 0; q < 3; q++) {
        int c = 2*lane + 64*q;
        float o0 = (v[q][0]-mean)*rstd*w[c]   + b[c];
        float o1 = (v[q][1]-mean)*rstd*w[c+1] + b[c+1];
        *reinterpret_cast<uint32_t*>(&g_h_bf[(size_t)tok*CDIM + c]) = packbf(o0, o1);
    }
}

// ---------------- bgemm: bf16 GEMM, 128x128 block, Ktile=32, 3-stage cp.async -----------
// flags: bit0 gelu | bit4 bf16 C store
#define ASTRIDE 10240
__global__ __launch_bounds__(256, 2) void bgemm_kernel(
    const bf16* __restrict__ A, const bf16* __restrict__ B, void* __restrict__ Cv,
    const float* __restrict__ bias, const float* __restrict__ addend,
    int M, int N, int K, int flags)
{
    GRID_SYNC();
    __shared__ uint32_t As[3][128][20];
    __shared__ uint32_t Bs[3][128][20];
    int tid = threadIdx.x;
    int m0 = blockIdx.y * 128, n0 = blockIdx.x * 128;

    int lrow = tid >> 1;
    int lk   = (tid & 1) * 16;
    int kb   = (tid & 1) * 8;
    const bf16* Ag = A + (size_t)(m0 + lrow) * K + lk;
    const bf16* Bg = B + (size_t)(n0 + lrow) * K + lk;
    uint32_t aDst0 = smem_u32(&As[0][lrow][kb]);
    uint32_t bDst0 = smem_u32(&Bs[0][lrow][kb]);

    int ntiles = K >> 5;
    #pragma unroll
    for (int s = 0; s < 2; s++) {
        cpa16(aDst0 + s*ASTRIDE,      Ag + s*32);
        cpa16(aDst0 + s*ASTRIDE + 16, Ag + s*32 + 8);
        cpa16(bDst0 + s*ASTRIDE,      Bg + s*32);
        cpa16(bDst0 + s*ASTRIDE + 16, Bg + s*32 + 8);
        CP_COMMIT();
    }

    int wid = tid >> 5, lane = tid & 31;
    int wm = wid >> 1, wn = wid & 1;
    int lr = lane >> 2, lc = lane & 3;

    uint32_t aAddr0[2], bAddr0[4];
    {
        int ar = (lane & 15);
        int ac = (lane >> 4) * 4;
        int br = ((lane >> 4) & 1) * 8 + (lane & 7);
        int bc = ((lane >> 3) & 1) * 4;
        #pragma unroll
        for (int mt = 0; mt < 2; mt++)
            aAddr0[mt] = smem_u32(&As[0][wm*32 + mt*16 + ar][ac]);
        #pragma unroll
        for (int np = 0; np < 4; np++)
            bAddr0[np] = smem_u32(&Bs[0][wn*64 + np*16 + br][bc]);
    }

    float acc[2][8][4];
    #pragma unroll
    for (int mt = 0; mt < 2; mt++)
        #pragma unroll
        for (int nt = 0; nt < 8; nt++)
            #pragma unroll
            for (int j = 0; j < 4; j++) acc[mt][nt][j] = 0.f;

    for (int k = 0; k < ntiles; k++) {
        CP_WAIT1();
        __syncthreads();
        int buf = (k % 3) * ASTRIDE;
        #pragma unroll
        for (int ks = 0; ks < 2; ks++) {
            int off = buf + ks*32;
            uint32_t afr[2][4];
            #pragma unroll
            for (int mt = 0; mt < 2; mt++)
                ldsm_x4(afr[mt][0], afr[mt][1], afr[mt][2], afr[mt][3], aAddr0[mt] + off);
            uint32_t bfr[8][2];
            #pragma unroll
            for (int np = 0; np < 4; np++)
                ldsm_x4(bfr[2*np][0], bfr[2*np][1], bfr[2*np+1][0], bfr[2*np+1][1], bAddr0[np] + off);
            #pragma unroll
            for (int mt = 0; mt < 2; mt++)
                #pragma unroll
                for (int nt = 0; nt < 8; nt++)
                    mma_bf16(acc[mt][nt], afr[mt], bfr[nt]);
        }
        int nk = k + 2;
        if (nk < ntiles) {
            int nb = (nk % 3) * ASTRIDE;
            cpa16(aDst0 + nb,      Ag + nk*32);
            cpa16(aDst0 + nb + 16, Ag + nk*32 + 8);
            cpa16(bDst0 + nb,      Bg + nk*32);
            cpa16(bDst0 + nb + 16, Bg + nk*32 + 8);
        }
        CP_COMMIT();
    }

    float* C = (float*)Cv;
    bf16*  Cb = (bf16*)Cv;
    #pragma unroll
    for (int nt = 0; nt < 8; nt++) {
        int col = n0 + wn*64 + nt*8 + lc*2;
        float b0 = 0.f, b1 = 0.f;
        if (bias) { b0 = bias[col]; b1 = bias[col+1]; }
        #pragma unroll
        for (int mt = 0; mt < 2; mt++) {
            int r0 = m0 + wm*32 + mt*16 + lr;
            int r1 = r0 + 8;
            float v00 = acc[mt][nt][0] + b0;
            float v01 = acc[mt][nt][1] + b1;
            float v10 = acc[mt][nt][2] + b0;
            float v11 = acc[mt][nt][3] + b1;
            if (addend) {
                const float* ad0 = addend + (size_t)r0*N + col;
                const float* ad1 = addend + (size_t)r1*N + col;
                v00 += ad0[0]; v01 += ad0[1];
                v10 += ad1[0]; v11 += ad1[1];
            }
            if (flags & 1) {
                v00 = 0.5f*v00*(1.f + erff(v00*0.70710678118654752f));
                v01 = 0.5f*v01*(1.f + erff(v01*0.70710678118654752f));
                v10 = 0.5f*v10*(1.f + erff(v10*0.70710678118654752f));
                v11 = 0.5f*v11*(1.f + erff(v11*0.70710678118654752f));
            }
            if (flags & 16) {
                *reinterpret_cast<uint32_t*>(&Cb[(size_t)r0*N + col]) = packbf(v00, v01);
                *reinterpret_cast<uint32_t*>(&Cb[(size_t)r1*N + col]) = packbf(v10, v11);
            } else {
                *reinterpret_cast<float2*>(&C[(size_t)r0*N + col]) = make_float2(v00, v01);
                *reinterpret_cast<float2*>(&C[(size_t)r1*N + col]) = make_float2(v10, v11);
            }
        }
    }
}

// ---------------- bgemm64: bf16 GEMM, 64x64 block, Ktile=32, 3-stage --------------------
// flags: bit0 gelu | bit2 transposed store
#define STRIDE64 5120
__global__ __launch_bounds__(256, 3) void bgemm64_kernel(
    const bf16* __restrict__ A, const bf16* __restrict__ B, float* __restrict__ C,
    const float* __restrict__ bias, const float* __restrict__ addend,
    int M, int N, int K, int flags)
{
    GRID_SYNC();
    __shared__ uint32_t As[3][64][20];
    __shared__ uint32_t Bs[3][64][20];
    int tid = threadIdx.x;
    int m0 = blockIdx.y * 64, n0 = blockIdx.x * 64;

    int lrow = tid >> 2;
    int lk   = (tid & 3) * 8;
    int kb   = (tid & 3) * 4;
    const bf16* Ag = A + (size_t)(m0 + lrow) * K + lk;
    const bf16* Bg = B + (size_t)(n0 + lrow) * K + lk;
    uint32_t aDst0 = smem_u32(&As[0][lrow][kb]);
    uint32_t bDst0 = smem_u32(&Bs[0][lrow][kb]);

    int ntiles = K >> 5;
    #pragma unroll
    for (int s = 0; s < 2; s++) {
        cpa16(aDst0 + s*STRIDE64, Ag + s*32);
        cpa16(bDst0 + s*STRIDE64, Bg + s*32);
        CP_COMMIT();
    }

    int wid = tid >> 5, lane = tid & 31;
    int wm = wid >> 1, wn = wid & 1;
    int lr = lane >> 2, lc = lane & 3;

    uint32_t aAddr0, bAddr0[2];
    {
        int ar = (lane & 15);
        int ac = (lane >> 4) * 4;
        int br = ((lane >> 4) & 1) * 8 + (lane & 7);
        int bc = ((lane >> 3) & 1) * 4;
        aAddr0 = smem_u32(&As[0][wm*16 + ar][ac]);
        #pragma unroll
        for (int np = 0; np < 2; np++)
            bAddr0[np] = smem_u32(&Bs[0][wn*32 + np*16 + br][bc]);
    }

    float acc[4][4];
    #pragma unroll
    for (int nt = 0; nt < 4; nt++)
        #pragma unroll
        for (int j = 0; j < 4; j++) acc[nt][j] = 0.f;

    for (int k = 0; k < ntiles; k++) {
        CP_WAIT1();
        __syncthreads();
        int buf = (k % 3) * STRIDE64;
        #pragma unroll
        for (int ks = 0; ks < 2; ks++) {
            int off = buf + ks*32;
            uint32_t afr[4];
            ldsm_x4(afr[0], afr[1], afr[2], afr[3], aAddr0 + off);
            uint32_t bfr[4][2];
            #pragma unroll
            for (int np = 0; np < 2; np++)
                ldsm_x4(bfr[2*np][0], bfr[2*np][1], bfr[2*np+1][0], bfr[2*np+1][1], bAddr0[np] + off);
            #pragma unroll
            for (int nt = 0; nt < 4; nt++)
                mma_bf16(acc[nt], afr, bfr[nt]);
        }
        int nk = k + 2;
        if (nk < ntiles) {
            int nb = (nk % 3) * STRIDE64;
            cpa16(aDst0 + nb, Ag + nk*32);
            cpa16(bDst0 + nb, Bg + nk*32);
        }
        CP_COMMIT();
    }

    #pragma unroll
    for (int nt = 0; nt < 4; nt++) {
        int col = n0 + wn*32 + nt*8 + lc*2;
        float b0 = 0.f, b1 = 0.f;
        if (bias) { b0 = bias[col]; b1 = bias[col+1]; }
        int r0 = m0 + wm*16 + lr;
        int r1 = r0 + 8;
        float v00 = acc[nt][0] + b0;
        float v01 = acc[nt][1] + b1;
        float v10 = acc[nt][2] + b0;
        float v11 = acc[nt][3] + b1;
        if (addend) {
            const float* ad0 = addend + (size_t)r0*N + col;
            const float* ad1 = addend + (size_t)r1*N + col;
            v00 += ad0[0]; v01 += ad0[1];
            v10 += ad1[0]; v11 += ad1[1];
        }
        if (flags & 1) {
            v00 = 0.5f*v00*(1.f + erff(v00*0.70710678118654752f));
            v01 = 0.5f*v01*(1.f + erff(v01*0.70710678118654752f));
            v10 = 0.5f*v10*(1.f + erff(v10*0.70710678118654752f));
            v11 = 0.5f*v11*(1.f + erff(v11*0.70710678118654752f));
        }
        if (flags & 4) {
            int bt0 = r0 / NSP, nn0 = r0 % NSP;
            int bt1 = r1 / NSP, nn1 = r1 % NSP;
            C[((size_t)bt0*CDIM + col  )*NSP + nn0] = v00;
            C[((size_t)bt0*CDIM + col+1)*NSP + nn0] = v01;
            C[((size_t)bt1*CDIM + col  )*NSP + nn1] = v10;
            C[((size_t)bt1*CDIM + col+1)*NSP + nn1] = v11;
        } else {
            *reinterpret_cast<float2*>(&C[(size_t)r0*N + col]) = make_float2(v00, v01);
            *reinterpret_cast<float2*>(&C[(size_t)r1*N + col]) = make_float2(v10, v11);
        }
    }
}

// ---------------- dbcdelta: dbc GEMM (N=64, K=384) + fused delta epilogue ----------------
__global__ __launch_bounds__(256, 2) void dbcdelta_kernel(const float* __restrict__ sdpb_g,
                                                          const float* __restrict__ tdpb_g)
{
    GRID_SYNC();
    __shared__ uint32_t As[3][64][20];
    __shared__ uint32_t Bs[3][64][20];
    __shared__ float sdt[64][DTR];
    __shared__ float sdpw[DTR*DI];
    __shared__ float sdpb[DI];
    int tid = threadIdx.x;
    int m0 = blockIdx.x * 64;
    int z  = blockIdx.z;
    const bf16* A = g_u_bf[z];
    const bf16* B = g_xpwP_bf[z];
    float* C      = g_dbc[z];
    float* delta  = g_delta[z];
    const float* dpw = g_dpwT[z];
    const float* dpb = z ? tdpb_g : sdpb_g;

    int lrow = tid >> 2;
    int lk   = (tid & 3) * 8;
    int kb   = (tid & 3) * 4;
    const bf16* Ag = A + (size_t)(m0 + lrow) * DI + lk;
    const bf16* Bg = B + (size_t)lrow * DI + lk;
    uint32_t aDst0 = smem_u32(&As[0][lrow][kb]);
    uint32_t bDst0 = smem_u32(&Bs[0][lrow][kb]);

    #pragma unroll
    for (int s = 0; s < 2; s++) {
        cpa16(aDst0 + s*STRIDE64, Ag + s*32);
        cpa16(bDst0 + s*STRIDE64, Bg + s*32);
        CP_COMMIT();
    }

    // stage small delta weights while pipeline runs
    for (int i = tid; i < DTR*DI; i += 256) sdpw[i] = dpw[i];
    for (int i = tid; i < DI; i += 256)     sdpb[i] = dpb[i];

    int wid = tid >> 5, lane = tid & 31;
    int wm = wid >> 1, wn = wid & 1;
    int lr = lane >> 2, lc = lane & 3;

    uint32_t aAddr0, bAddr0[2];
    {
        int ar = (lane & 15);
        int ac = (lane >> 4) * 4;
        int br = ((lane >> 4) & 1) * 8 + (lane & 7);
        int bc = ((lane >> 3) & 1) * 4;
        aAddr0 = smem_u32(&As[0][wm*16 + ar][ac]);
        #pragma unroll
        for (int np = 0; np < 2; np++)
            bAddr0[np] = smem_u32(&Bs[0][wn*32 + np*16 + br][bc]);
    }

    float acc[4][4];
    #pragma unroll
    for (int nt = 0; nt < 4; nt++)
        #pragma unroll
        for (int j = 0; j < 4; j++) acc[nt][j] = 0.f;

    const int ntiles = DI >> 5;   // 12
    for (int k = 0; k < ntiles; k++) {
        CP_WAIT1();
        __syncthreads();
        int buf = (k % 3) * STRIDE64;
        #pragma unroll
        for (int ks = 0; ks < 2; ks++) {
            int off = buf + ks*32;
            uint32_t afr[4];
            ldsm_x4(afr[0], afr[1], afr[2], afr[3], aAddr0 + off);
            uint32_t bfr[4][2];
            #pragma unroll
            for (int np = 0; np < 2; np++)
                ldsm_x4(bfr[2*np][0], bfr[2*np][1], bfr[2*np+1][0], bfr[2*np+1][1], bAddr0[np] + off);
            #pragma unroll
            for (int nt = 0; nt < 4; nt++)
                mma_bf16(acc[nt], afr, bfr[nt]);
        }
        int nk = k + 2;
        if (nk < ntiles) {
            int nb = (nk % 3) * STRIDE64;
            cpa16(aDst0 + nb, Ag + nk*32);
            cpa16(bDst0 + nb, Bg + nk*32);
        }
        CP_COMMIT();
    }

    // store dbc + stage dt (cols 0..11) into smem
    #pragma unroll
    for (int nt = 0; nt < 4; nt++) {
        int col = wn*32 + nt*8 + lc*2;
        int r0l = wm*16 + lr;
        int r1l = r0l + 8;
        *reinterpret_cast<float2*>(&C[(size_t)(m0 + r0l)*64 + col]) = make_float2(acc[nt][0], acc[nt][1]);
        *reinterpret_cast<float2*>(&C[(size_t)(m0 + r1l)*64 + col]) = make_float2(acc[nt][2], acc[nt][3]);
        if (wn == 0 && col + 1 < DTR) {
            sdt[r0l][col] = acc[nt][0]; sdt[r0l][col+1] = acc[nt][1];
            sdt[r1l][col] = acc[nt][2]; sdt[r1l][col+1] = acc[nt][3];
        }
    }
    __syncthreads();

    // delta = softplus(dt @ dpw^T + dpb) for 64 tokens x 384 d
    #pragma unroll
    for (int half = 0; half < 2; half++) {
        int d = tid + half*256;
        if (d < DI) {
            float base = sdpb[d];
            float w[DTR];
            #pragma unroll
            for (int rr = 0; rr < DTR; rr++) w[rr] = sdpw[rr*DI + d];
            #pragma unroll 4
            for (int t = 0; t < 64; t++) {
                float a2 = base;
                #pragma unroll
                for (int rr = 0; rr < DTR; rr++) a2 = fmaf(sdt[t][rr], w[rr], a2);
                delta[(size_t)(m0 + t)*DI + d] = (a2 > 15.f) ? a2 : log1pf(__expf(a2));
            }
        }
    }
}

// ---------------- conv4 depthwise + silu (4 tokens/block) ----------------
__global__ __launch_bounds__(384) void conv_kernel(const float* __restrict__ scb,
                                                   const float* __restrict__ tcb)
{
    GRID_SYNC();
    int m = blockIdx.y;
    int tid = threadIdx.x;
    int rl = tid / 96, v = tid % 96;
    int r = blockIdx.x * 4 + rl;
    int pos  = m ? ((r / NSP) & (TT-1)) : (r % NSP);
    int strd = m ? NSP : 1;
    const float* cb = m ? tcb : scb;
    float4 acc = *reinterpret_cast<const float4*>(&cb[4*v]);
    #pragma unroll
    for (int k = 0; k < 4; k++) {
        if (pos - 3 + k >= 0) {
            const bf16* xp = &g_xz_bf[(size_t)(r - (3-k)*strd)*XZW + m*768 + 4*v];
            uint2 raw = *reinterpret_cast<const uint2*>(xp);
            float2 x01 = __bfloat1622float2(*reinterpret_cast<const __nv_bfloat162*>(&raw.x));
            float2 x23 = __bfloat1622float2(*reinterpret_cast<const __nv_bfloat162*>(&raw.y));
            float4 cw = *reinterpret_cast<const float4*>(&g_cwT[m][k*DI + 4*v]);
            acc.x = fmaf(cw.x, x01.x, acc.x);
            acc.y = fmaf(cw.y, x01.y, acc.y);
            acc.z = fmaf(cw.z, x23.x, acc.z);
            acc.w = fmaf(cw.w, x23.y, acc.w);
        }
    }
    acc.x = acc.x / (1.f + __expf(-acc.x));
    acc.y = acc.y / (1.f + __expf(-acc.y));
    acc.z = acc.z / (1.f + __expf(-acc.z));
    acc.w = acc.w / (1.f + __expf(-acc.w));
    uint2 pk = make_uint2(packbf(acc.x, acc.y), packbf(acc.z, acc.w));
    *reinterpret_cast<uint2*>(&g_u_bf[m][(size_t)r*DI + 4*v]) = pk;
}

// ---------------- merged scans ----------------
#define SPATIAL_BLOCKS 768
__global__ __launch_bounds__(128) void scan_kernel(const float* __restrict__ sD,
                                                   const float* __restrict__ tD)
{
    GRID_SYNC();
    int bx = blockIdx.x;
    int tid = threadIdx.x;

    if (bx < SPATIAL_BLOCKS) {
        __shared__ float sbuf[64][8];
        int s   = bx / 48;
        int dpg = bx % 48;
        int w = tid >> 5, lane = tid & 31;
        int sub = lane >> 4, n = lane & 15;
        int d = dpg*8 + w*2 + sub;
        int ycol0 = dpg*8;

        float a  = g_A[0][d*DS + n];
        float Dd = sD[d];
        const float* delta = g_delta[0];
        const bf16*  u     = g_u_bf[0];
        const float* dbc   = g_dbc[0];
        int base = s * NSP;

        float dl[4], uu[4], Bv[4], Cv[4];
        #pragma unroll
        for (int j = 0; j < 4; j++) {
            size_t r = base + j;
            dl[j] = __ldg(&delta[r*DI + d]);
            uu[j] = __bfloat162float(u[r*DI + d]);
            Bv[j] = __ldg(&dbc[r*64 + DTR + n]);
            Cv[j] = __ldg(&dbc[r*64 + DTR + DS + n]);
        }

        float h = 0.f;
        for (int pos = 0; pos < NSP; pos += 4) {
            float ndl[4], nuu[4], nBv[4], nCv[4];
            if (pos + 4 < NSP) {
                #pragma unroll
                for (int j = 0; j < 4; j++) {
                    size_t r = base + pos + 4 + j;
                    ndl[j] = __ldg(&delta[r*DI + d]);
                    nuu[j] = __bfloat162float(u[r*DI + d]);
                    nBv[j] = __ldg(&dbc[r*64 + DTR + n]);
                    nCv[j] = __ldg(&dbc[r*64 + DTR + DS + n]);
                }
            }
            float dA[4], dBu[4];
            #pragma unroll
            for (int j = 0; j < 4; j++) {
                dA[j]  = __expf(dl[j] * a);
                dBu[j] = dl[j] * uu[j] * Bv[j];
            }
            float part[4];
            #pragma unroll
            for (int j = 0; j < 4; j++) {
                h = fmaf(h, dA[j], dBu[j]);
                part[j] = h * Cv[j];
            }
            #pragma unroll
            for (int off = 1; off <= 8; off <<= 1)
                #pragma unroll
                for (int j = 0; j < 4; j++)
                    part[j] += __shfl_xor_sync(0xffffffffu, part[j], off);
            if (n == 0) {
                #pragma unroll
                for (int j = 0; j < 4; j++)
                    sbuf[(pos + j) & 63][w*2 + sub] = part[j] + uu[j] * Dd;
            }
            if ((pos & 63) == 60) {
                __syncthreads();
                int p2 = tid >> 1, half = tid & 1;
                size_t r = base + (pos & ~63) + p2;
                float4 v = *reinterpret_cast<float4*>(&sbuf[p2][half*4]);
                uint2 zraw = *reinterpret_cast<const uint2*>(&g_xz_bf[r*XZW + 384 + ycol0 + half*4]);
                float2 z01 = __bfloat1622float2(*reinterpret_cast<const __nv_bfloat162*>(&zraw.x));
                float2 z23 = __bfloat1622float2(*reinterpret_cast<const __nv_bfloat162*>(&zraw.y));
                v.x *= z01.x / (1.f + __expf(-z01.x));
                v.y *= z01.y / (1.f + __expf(-z01.y));
                v.z *= z23.x / (1.f + __expf(-z23.x));
                v.w *= z23.y / (1.f + __expf(-z23.y));
                uint2 pk = make_uint2(packbf(v.x, v.y), packbf(v.z, v.w));
                *reinterpret_cast<uint2*>(&g_y_bf[r*(2*DI) + ycol0 + half*4]) = pk;
                __syncthreads();
            }
            #pragma unroll
            for (int j = 0; j < 4; j++) {
                dl[j] = ndl[j]; uu[j] = nuu[j]; Bv[j] = nBv[j]; Cv[j] = nCv[j];
            }
        }
    } else {
        int b2 = bx - SPATIAL_BLOCKS;
        int seq = b2 / 3;
        int d = (b2 % 3) * 128 + tid;
        int lane = tid & 31;
        int b = seq / NSP, nsp = seq % NSP;
        int base = b * (TT*NSP) + nsp;

        float a[DS];
        #pragma unroll
        for (int q = 0; q < 4; q++)
            *reinterpret_cast<float4*>(&a[q*4]) = *reinterpret_cast<const float4*>(&g_A[1][d*DS + q*4]);
        float Dd = tD[d];
        const float* delta = g_delta[1];
        const bf16*  u     = g_u_bf[1];
        const float* dbc   = g_dbc[1];

        float h[DS];
        #pragma unroll
        for (int q = 0; q < DS; q++) h[q] = 0.f;

        for (int t = 0; t < TT; t++) {
            size_t r = base + (size_t)t * NSP;
            float dl = delta[r*DI + d];
            float uu = __bfloat162float(u[r*DI + d]);
            float bc = dbc[r*64 + DTR + lane];
            float dlu = dl * uu;
            float y = 0.f;
            #pragma unroll
            for (int q = 0; q < DS; q++) {
                float Bn = __shfl_sync(0xffffffffu, bc, q);
                float Cn = __shfl_sync(0xffffffffu, bc, q + 16);
                float dA = __expf(dl * a[q]);
                h[q] = fmaf(h[q], dA, dlu * Bn);
                y = fmaf(h[q], Cn, y);
            }
            float z = __bfloat162float(g_xz_bf[r*XZW + 1152 + d]);
            float g = z / (1.f + __expf(-z));
            g_y_bf[r*(2*DI) + DI + d] = __float2bfloat16((y + uu * Dd) * g);
        }
    }
}

// ---------------- PDL launch helper ----------------
template <typename F, typename... Args>
static inline void pdl_launch(dim3 grid, dim3 block, F func, Args... args)
{
    cudaLaunchConfig_t cfg = {};
    cfg.gridDim = grid;
    cfg.blockDim = block;
    cfg.dynamicSmemBytes = 0;
    cfg.stream = 0;
    cudaLaunchAttribute at[1];
    at[0].id = cudaLaunchAttributeProgrammaticStreamSerialization;
    at[0].val.programmaticStreamSerializationAllowed = 1;
    cfg.attrs = at;
    cfg.numAttrs = 1;
    cudaLaunchKernelEx(&cfg, func, args...);
}

// ---------------- host launcher ----------------
extern "C" void kernel_launch(void* const* d_in, const int* in_sizes, int n_in,
                              void* d_out, int out_size)
{
    const float* x_in   = (const float*)d_in[0];
    const float* n1w    = (const float*)d_in[1];
    const float* n1b    = (const float*)d_in[2];
    const float* s_inw  = (const float*)d_in[3];
    const float* s_cw   = (const float*)d_in[4];
    const float* s_cb   = (const float*)d_in[5];
    const float* s_xpw  = (const float*)d_in[6];
    const float* s_dpw  = (const float*)d_in[7];
    const float* s_dpb  = (const float*)d_in[8];
    const float* s_Alog = (const float*)d_in[9];
    const float* s_D    = (const float*)d_in[10];
    const float* s_outw = (const float*)d_in[11];
    const float* t_inw  = (const float*)d_in[12];
    const float* t_cw   = (const float*)d_in[13];
    const float* t_cb   = (const float*)d_in[14];
    const float* t_xpw  = (const float*)d_in[15];
    const float* t_dpw  = (const float*)d_in[16];
    const float* t_dpb  = (const float*)d_in[17];
    const float* t_Alog = (const float*)d_in[18];
    const float* t_D    = (const float*)d_in[19];
    const float* t_outw = (const float*)d_in[20];
    const float* fw     = (const float*)d_in[21];
    const float* fb     = (const float*)d_in[22];
    const float* n2w    = (const float*)d_in[23];
    const float* n2b    = (const float*)d_in[24];
    const float* w1     = (const float*)d_in[25];
    const float* b1     = (const float*)d_in[26];
    const float* w2     = (const float*)d_in[27];
    const float* b2     = (const float*)d_in[28];
    float* out = (float*)d_out;

    bf16 *p_xn_bf, *p_xz_bf, *p_y_bf, *p_h_bf, *p_hid_bf, *p_Win_bf, *p_W12_bf, *p_w1_bf, *p_w2_bf;
    float *p_short, *p_x2;
    cudaGetSymbolAddress((void**)&p_xn_bf, g_xn_bf);
    cudaGetSymbolAddress((void**)&p_short, g_short);
    cudaGetSymbolAddress((void**)&p_xz_bf, g_xz_bf);
    cudaGetSymbolAddress((void**)&p_y_bf,  g_y_bf);
    cudaGetSymbolAddress((void**)&p_x2,    g_x2);
    cudaGetSymbolAddress((void**)&p_h_bf,  g_h_bf);
    cudaGetSymbolAddress((void**)&p_hid_bf,g_hid_bf);
    cudaGetSymbolAddress((void**)&p_Win_bf,g_Win_bf);
    cudaGetSymbolAddress((void**)&p_W12_bf,g_W12_bf);
    cudaGetSymbolAddress((void**)&p_w1_bf, g_w1_bf);
    cudaGetSymbolAddress((void**)&p_w2_bf, g_w2_bf);

    // 0. prep + fold merged
    pdl_launch(dim3(816), dim3(384), prepfold_kernel,
               s_Alog, t_Alog, s_cw, t_cw, s_dpw, t_dpw,
               s_inw, t_inw, s_xpw, t_xpw, w1, w2, fw, s_outw, t_outw);

    // 1. transpose + LN1
    pdl_launch(dim3(16, 18), dim3(256), ln1_kernel, x_in, n1w, n1b);

    // 2. merged in_proj GEMM (N=1536, K=192) -> bf16 xz
    pdl_launch(dim3(XZW/128, TOK/128), dim3(256), bgemm_kernel,
               (const bf16*)p_xn_bf, (const bf16*)p_Win_bf, (void*)p_xz_bf,
               (const float*)nullptr, (const float*)nullptr, TOK, XZW, CDIM, 16);

    // 3. conv+silu (4 tokens/block)
    pdl_launch(dim3(TOK/4, 2), dim3(384), conv_kernel, s_cb, t_cb);

    // 4. dbc GEMM + fused delta (both mambas via z)
    pdl_launch(dim3(TOK/64, 1, 2), dim3(256), dbcdelta_kernel, s_dpb, t_dpb);

    // 5. scans
    pdl_launch(dim3(SPATIAL_BLOCKS + 3456), dim3(128), scan_kernel, s_D, t_D);

    // 6. fusion + residual (N=192, K=768)
    pdl_launch(dim3(3, TOK/64), dim3(256), bgemm64_kernel,
               (const bf16*)p_y_bf, (const bf16*)p_W12_bf, p_x2,
               fb, (const float*)p_short, TOK, CDIM, 2*DI, 0);

    // 7. LN2 + MLP
    pdl_launch(dim3(TOK/4), dim3(128), ln2_kernel, (const float*)p_x2, n2w, n2b);
    pdl_launch(dim3(MLPH/128, TOK/128), dim3(256), bgemm_kernel,
               (const bf16*)p_h_bf, (const bf16*)p_w1_bf, (void*)p_hid_bf,
               b1, (const float*)nullptr, TOK, MLPH, CDIM, 1 | 16);
    pdl_launch(dim3(3, TOK/64), dim3(256), bgemm64_kernel,
               (const bf16*)p_hid_bf, (const bf16*)p_w2_bf, out,
               b2, (const float*)p_x2, TOK, CDIM, MLPH, 4);
}